// round 4
// baseline (speedup 1.0000x reference)
#include <cuda_runtime.h>
#include <cstdint>

#define NIDS   1000000
#define ZCH    400000
#define DIM    128
#define TOTAL  (2 * NIDS)
#define HASHSZ 4000000
#define NCHUNK (TOTAL / 32)      // 62500 warp-chunks
#define GROUP  4
#define NGROUP (NCHUNK / GROUP)  // 15625 (exact)

// Static scratch (no allocations allowed). Zero-initialized at module load.
// inv maps store slot+1; 0 means "unmatched" -> collision slot ZCH-1.
// Entries are rewritten identically by scatter_kernel on every launch.
__device__ double   g_acc;
__device__ unsigned g_done;
__device__ int      g_inv0[HASHSZ];
__device__ int      g_inv1[HASHSZ];

// Table values < 4M < 2^22: if the buffer is int64, the odd 32-bit words of
// the first entries are all 0; sorted random int32 data -> essentially never.
__device__ __forceinline__ bool sniff_is64(const unsigned* __restrict__ w) {
    return (w[1] | w[3] | w[5] | w[7]) == 0u;
}

// ---------------------------------------------------------------------------
// 1) Scatter slot+1 into the inverse maps. lower_bound semantics: first
//    occurrence wins for duplicates (branch on sorted neighbor, no atomics).
// ---------------------------------------------------------------------------
__global__ __launch_bounds__(256) void scatter_kernel(
    const void* __restrict__ m0v, const void* __restrict__ m1v)
{
    const int tid = blockIdx.x * blockDim.x + threadIdx.x;
    if (tid >= 2 * ZCH) return;
    const int feat = (tid >= ZCH) ? 1 : 0;
    const int j    = feat ? (tid - ZCH) : tid;
    const void* mv = feat ? m1v : m0v;
    int* inv       = feat ? g_inv1 : g_inv0;

    const bool is64 = sniff_is64((const unsigned*)m0v);
    int id, prev = -1;
    if (is64) {
        const long long* m = (const long long*)mv;
        id = (int)m[j];
        if (j > 0) prev = (int)m[j - 1];
    } else {
        const int* m = (const int*)mv;
        id = m[j];
        if (j > 0) prev = m[j - 1];
    }
    if (j == 0 || prev != id) inv[id] = j + 1;
}

// ---------------------------------------------------------------------------
// 2) Main: 4-chunk batched id/inv loads (MLP=4 on both random stages),
//    software-pipelined cold-row gather (prefetch depth 2, float4 acc),
//    hot-row contribution folded algebraically, last-block finalize.
// ---------------------------------------------------------------------------
__global__ __launch_bounds__(256) void sparse_arch_kernel(
    const void* __restrict__ ids0v, const void* __restrict__ ids1v,
    const void* __restrict__ m0v,
    const float* __restrict__ e0,   const float* __restrict__ e1,
    float* __restrict__ out)
{
    __shared__ double blk_acc;
    if (threadIdx.x == 0) blk_acc = 0.0;
    __syncthreads();

    const int  lane = threadIdx.x & 31;
    const int  wpb  = blockDim.x >> 5;
    const int  wg   = blockIdx.x * wpb + (threadIdx.x >> 5);
    const int  nw   = gridDim.x * wpb;
    const bool is64 = sniff_is64((const unsigned*)m0v);

    // Collision-row sums (broadcast to all lanes), computed once per warp.
    const float4 h0 = ((const float4*)(e0 + (size_t)(ZCH - 1) * DIM))[lane];
    const float4 h1 = ((const float4*)(e1 + (size_t)(ZCH - 1) * DIM))[lane];
    float hs0 = (h0.x + h0.y) + (h0.z + h0.w);
    float hs1 = (h1.x + h1.y) + (h1.z + h1.w);
    #pragma unroll
    for (int o = 16; o > 0; o >>= 1) {
        hs0 += __shfl_xor_sync(0xffffffffu, hs0, o);
        hs1 += __shfl_xor_sync(0xffffffffu, hs1, o);
    }

    float4    acc  = make_float4(0.f, 0.f, 0.f, 0.f);
    long long hot0 = 0, hot1 = 0;

    // NIDS % 32 == 0: every 32-id chunk lies entirely within one feature.
    for (int g = wg; g < NGROUP; g += nw) {
        const int base = g * (GROUP * 32) + lane;

        int      ft[GROUP], idv[GROUP], cell[GROUP], slot[GROUP];
        unsigned hotm[GROUP];

        // Stage 1: 4 independent (coalesced) id loads.
        #pragma unroll
        for (int c = 0; c < GROUP; ++c) {
            const int idx = base + c * 32;
            const int f   = (idx >= NIDS) ? 1 : 0;
            const int i   = idx - (f ? NIDS : 0);
            ft[c] = f;
            const void* idsv = f ? ids1v : ids0v;
            if (is64) idv[c] = (int)((const long long*)idsv)[i];
            else      idv[c] = ((const int*)idsv)[i];
        }

        // Stage 2: 4 independent random inv loads (the latency hot spot).
        #pragma unroll
        for (int c = 0; c < GROUP; ++c)
            cell[c] = (ft[c] ? g_inv1 : g_inv0)[idv[c]];

        // Stage 3: slots, output writes, hot masks.
        #pragma unroll
        for (int c = 0; c < GROUP; ++c) {
            const int sl = cell[c] ? (cell[c] - 1) : (ZCH - 1);
            slot[c] = sl;
            out[1 + base + c * 32] = (float)sl;
            hotm[c] = __ballot_sync(0xffffffffu, sl == ZCH - 1);
            if (ft[c]) hot1 += __popc(hotm[c]); else hot0 += __popc(hotm[c]);
        }

        // Stage 4: pipelined cold-row gathers (prefetch next row's float4
        // before consuming the current one).
        #pragma unroll
        for (int c = 0; c < GROUP; ++c) {
            unsigned nh = ~hotm[c];
            const float* e = ft[c] ? e1 : e0;
            if (nh) {
                int j = __ffs(nh) - 1; nh &= nh - 1;
                int sl = __shfl_sync(0xffffffffu, slot[c], j);
                float4 v = ((const float4*)(e + (size_t)sl * DIM))[lane];
                while (nh) {
                    const int j2 = __ffs(nh) - 1; nh &= nh - 1;
                    const int sl2 = __shfl_sync(0xffffffffu, slot[c], j2);
                    const float4 v2 =
                        ((const float4*)(e + (size_t)sl2 * DIM))[lane];
                    acc.x += v.x; acc.y += v.y; acc.z += v.z; acc.w += v.w;
                    v = v2;
                }
                acc.x += v.x; acc.y += v.y; acc.z += v.z; acc.w += v.w;
            }
        }
    }

    float s = (acc.x + acc.y) + (acc.z + acc.w);
    #pragma unroll
    for (int o = 16; o > 0; o >>= 1)
        s += __shfl_down_sync(0xffffffffu, s, o);

    if (lane == 0) {
        const double t = (double)s
                       + (double)hot0 * (double)hs0
                       + (double)hot1 * (double)hs1;
        atomicAdd(&blk_acc, t);
    }
    __syncthreads();

    if (threadIdx.x == 0) {
        atomicAdd(&g_acc, blk_acc);
        __threadfence();
        const unsigned done = atomicAdd(&g_done, 1u);
        if (done == gridDim.x - 1) {              // last block finalizes
            const double total = atomicAdd(&g_acc, 0.0);
            out[0] = (float)(total / ((double)TOTAL * (double)DIM));
            g_acc  = 0.0;                          // reset for next replay
            g_done = 0u;
        }
    }
}

// ---------------------------------------------------------------------------
// Launch: 2 kernels, graph-capturable, allocation-free.
// Inputs (metadata order): ids_0, ids_1, mch_ids_0, mch_ids_1, emb_0, emb_1
// Output: [loss, remapped_0 (1M), remapped_1 (1M)] as float32.
// ---------------------------------------------------------------------------
extern "C" void kernel_launch(void* const* d_in, const int* in_sizes, int n_in,
                              void* d_out, int out_size)
{
    const void*  ids0 = d_in[0];
    const void*  ids1 = d_in[1];
    const void*  m0   = d_in[2];
    const void*  m1   = d_in[3];
    const float* e0   = (const float*)d_in[4];
    const float* e1   = (const float*)d_in[5];
    float* out = (float*)d_out;

    const int threads = 256;
    scatter_kernel<<<(2 * ZCH + threads - 1) / threads, threads>>>(m0, m1);
    sparse_arch_kernel<<<148 * 8, threads>>>(ids0, ids1, m0, e0, e1, out);
}

// round 5
// speedup vs baseline: 1.2184x; 1.2184x over previous
#include <cuda_runtime.h>
#include <cstdint>

#define NIDS   1000000
#define ZCH    400000
#define DIM    128
#define TOTAL  (2 * NIDS)
#define HASHSZ 4000000

// Static scratch (no allocations allowed). Zero-initialized at module load.
// inv maps store slot+1; 0 means "unmatched" -> collision slot ZCH-1.
// Entries are rewritten identically by scatter_kernel on every launch.
__device__ double   g_acc;
__device__ unsigned g_done;
__device__ int      g_inv0[HASHSZ];
__device__ int      g_inv1[HASHSZ];

// Table values < 4M < 2^22: if the buffer is int64, the odd 32-bit words of
// the first entries are all 0; sorted random int32 data -> essentially never.
__device__ __forceinline__ bool sniff_is64(const unsigned* __restrict__ w) {
    return (w[1] | w[3] | w[5] | w[7]) == 0u;
}

// ---------------------------------------------------------------------------
// 1) Scatter slot+1 into the inverse maps. lower_bound semantics: first
//    occurrence wins for duplicates (branch on sorted neighbor, no atomics).
// ---------------------------------------------------------------------------
__global__ __launch_bounds__(256) void scatter_kernel(
    const void* __restrict__ m0v, const void* __restrict__ m1v)
{
    const int tid = blockIdx.x * blockDim.x + threadIdx.x;
    if (tid >= 2 * ZCH) return;
    const int feat = (tid >= ZCH) ? 1 : 0;
    const int j    = feat ? (tid - ZCH) : tid;
    const void* mv = feat ? m1v : m0v;
    int* inv       = feat ? g_inv1 : g_inv0;

    const bool is64 = sniff_is64((const unsigned*)m0v);
    int id, prev = -1;
    if (is64) {
        const long long* m = (const long long*)mv;
        id = (int)m[j];
        if (j > 0) prev = (int)m[j - 1];
    } else {
        const int* m = (const int*)mv;
        id = m[j];
        if (j > 0) prev = m[j - 1];
    }
    if (j == 0 || prev != id) inv[id] = j + 1;
}

// ---------------------------------------------------------------------------
// 2) Main (R3 shape, low-register): O(1) remap, hot-row contribution folded
//    algebraically, cold rows gathered warp-cooperatively with streaming
//    (evict-first) cache hints so use-once data doesn't evict the inv maps.
// ---------------------------------------------------------------------------
__global__ __launch_bounds__(256) void sparse_arch_kernel(
    const void* __restrict__ ids0v, const void* __restrict__ ids1v,
    const void* __restrict__ m0v,
    const float* __restrict__ e0,   const float* __restrict__ e1,
    float* __restrict__ out)
{
    __shared__ double blk_acc;
    if (threadIdx.x == 0) blk_acc = 0.0;
    __syncthreads();

    const int  lane = threadIdx.x & 31;
    const int  wpb  = blockDim.x >> 5;
    const int  wg   = blockIdx.x * wpb + (threadIdx.x >> 5);
    const int  nw   = gridDim.x * wpb;
    const bool is64 = sniff_is64((const unsigned*)m0v);

    // Collision-row sums (broadcast to all lanes), computed once per warp.
    const float4 h0 = ((const float4*)(e0 + (size_t)(ZCH - 1) * DIM))[lane];
    const float4 h1 = ((const float4*)(e1 + (size_t)(ZCH - 1) * DIM))[lane];
    float hs0 = (h0.x + h0.y) + (h0.z + h0.w);
    float hs1 = (h1.x + h1.y) + (h1.z + h1.w);
    #pragma unroll
    for (int o = 16; o > 0; o >>= 1) {
        hs0 += __shfl_xor_sync(0xffffffffu, hs0, o);
        hs1 += __shfl_xor_sync(0xffffffffu, hs1, o);
    }

    float     s    = 0.0f;
    long long hot0 = 0, hot1 = 0;

    // NIDS % 32 == 0: every 32-id chunk lies entirely within one feature.
    for (int base = wg * 32; base < TOTAL; base += nw * 32) {
        const int idx  = base + lane;
        const int feat = (idx >= NIDS) ? 1 : 0;
        const int i    = feat ? (idx - NIDS) : idx;

        const void* idsv = feat ? ids1v : ids0v;
        const int*  inv  = feat ? g_inv1 : g_inv0;

        // Streaming id load (use-once).
        int id;
        if (is64) id = (int)__ldcs((const long long*)idsv + i);
        else      id = __ldcs((const int*)idsv + i);

        // Cached random inv load (the data we WANT resident in L2).
        const int cell = __ldg(inv + id);
        const int slot = cell ? (cell - 1) : (ZCH - 1);
        __stcs(out + 1 + idx, (float)slot);   // write-once, evict-first

        const unsigned hotm = __ballot_sync(0xffffffffu, slot == ZCH - 1);
        if (feat) hot1 += __popc(hotm); else hot0 += __popc(hotm);

        // Gather only the cold rows (~3 of 32 on average), 512B coalesced,
        // streaming hint (each row read exactly once).
        unsigned nh = ~hotm;
        const float* e = feat ? e1 : e0;
        while (nh) {
            const int j = __ffs(nh) - 1;
            nh &= nh - 1;
            const int sl = __shfl_sync(0xffffffffu, slot, j);
            const float4 v = __ldcs((const float4*)(e + (size_t)sl * DIM) + lane);
            s += (v.x + v.y) + (v.z + v.w);
        }
    }

    #pragma unroll
    for (int o = 16; o > 0; o >>= 1)
        s += __shfl_down_sync(0xffffffffu, s, o);

    if (lane == 0) {
        const double t = (double)s
                       + (double)hot0 * (double)hs0
                       + (double)hot1 * (double)hs1;
        atomicAdd(&blk_acc, t);
    }
    __syncthreads();

    if (threadIdx.x == 0) {
        atomicAdd(&g_acc, blk_acc);
        __threadfence();
        const unsigned done = atomicAdd(&g_done, 1u);
        if (done == gridDim.x - 1) {              // last block finalizes
            const double total = atomicAdd(&g_acc, 0.0);
            out[0] = (float)(total / ((double)TOTAL * (double)DIM));
            g_acc  = 0.0;                          // reset for next replay
            g_done = 0u;
        }
    }
}

// ---------------------------------------------------------------------------
// Launch: 2 kernels, graph-capturable, allocation-free.
// Inputs (metadata order): ids_0, ids_1, mch_ids_0, mch_ids_1, emb_0, emb_1
// Output: [loss, remapped_0 (1M), remapped_1 (1M)] as float32.
// ---------------------------------------------------------------------------
extern "C" void kernel_launch(void* const* d_in, const int* in_sizes, int n_in,
                              void* d_out, int out_size)
{
    const void*  ids0 = d_in[0];
    const void*  ids1 = d_in[1];
    const void*  m0   = d_in[2];
    const void*  m1   = d_in[3];
    const float* e0   = (const float*)d_in[4];
    const float* e1   = (const float*)d_in[5];
    float* out = (float*)d_out;

    const int threads = 256;
    scatter_kernel<<<(2 * ZCH + threads - 1) / threads, threads>>>(m0, m1);
    sparse_arch_kernel<<<148 * 8, threads>>>(ids0, ids1, m0, e0, e1, out);
}

// round 6
// speedup vs baseline: 1.2600x; 1.0341x over previous
#include <cuda_runtime.h>
#include <cstdint>

#define NIDS   1000000
#define ZCH    400000
#define DIM    128
#define TOTAL  (2 * NIDS)
#define HASHSZ 4000000

// Static scratch (no allocations allowed). Zero-initialized at module load.
// inv maps store slot+1; 0 means "unmatched" -> collision slot ZCH-1.
// Entries are rewritten identically by scatter_kernel on every launch.
__device__ double   g_acc;
__device__ unsigned g_done;
__device__ int      g_inv0[HASHSZ];
__device__ int      g_inv1[HASHSZ];

// Table values < 4M < 2^22: if the buffer is int64, the odd 32-bit words of
// the first entries are all 0; sorted random int32 data -> essentially never.
__device__ __forceinline__ bool sniff_is64(const unsigned* __restrict__ w) {
    return (w[1] | w[3] | w[5] | w[7]) == 0u;
}

// ---------------------------------------------------------------------------
// 1) Scatter slot+1 into the inverse maps. lower_bound semantics: first
//    occurrence wins for duplicates (branch on sorted neighbor, no atomics).
// ---------------------------------------------------------------------------
__global__ __launch_bounds__(256) void scatter_kernel(
    const void* __restrict__ m0v, const void* __restrict__ m1v)
{
    const int tid = blockIdx.x * blockDim.x + threadIdx.x;
    if (tid >= 2 * ZCH) return;
    const int feat = (tid >= ZCH) ? 1 : 0;
    const int j    = feat ? (tid - ZCH) : tid;
    const void* mv = feat ? m1v : m0v;
    int* inv       = feat ? g_inv1 : g_inv0;

    const bool is64 = sniff_is64((const unsigned*)m0v);
    int id, prev = -1;
    if (is64) {
        const long long* m = (const long long*)mv;
        id = (int)m[j];
        if (j > 0) prev = (int)m[j - 1];
    } else {
        const int* m = (const int*)mv;
        id = m[j];
        if (j > 0) prev = m[j - 1];
    }
    if (j == 0 || prev != id) inv[id] = j + 1;
}

// ---------------------------------------------------------------------------
// 2) Main: depth-1 software pipeline across warp-chunks — chunk n+1's
//    id->inv random-load chain is issued before chunk n's gather work, so
//    the ~1000-cycle latency hides behind real work. Gather loop prefetches
//    the next row before consuming the current one. Hot-row contribution
//    folded algebraically; last-block finalize (graph-replay safe).
// ---------------------------------------------------------------------------
__global__ __launch_bounds__(256) void sparse_arch_kernel(
    const void* __restrict__ ids0v, const void* __restrict__ ids1v,
    const void* __restrict__ m0v,
    const float* __restrict__ e0,   const float* __restrict__ e1,
    float* __restrict__ out)
{
    __shared__ double blk_acc;
    if (threadIdx.x == 0) blk_acc = 0.0;
    __syncthreads();

    const int  lane = threadIdx.x & 31;
    const int  wpb  = blockDim.x >> 5;
    const int  wg   = blockIdx.x * wpb + (threadIdx.x >> 5);
    const int  nw   = gridDim.x * wpb;
    const int  step = nw * 32;
    const bool is64 = sniff_is64((const unsigned*)m0v);

    // Collision-row sums (broadcast to all lanes), computed once per warp.
    const float4 h0 = ((const float4*)(e0 + (size_t)(ZCH - 1) * DIM))[lane];
    const float4 h1 = ((const float4*)(e1 + (size_t)(ZCH - 1) * DIM))[lane];
    float hs0 = (h0.x + h0.y) + (h0.z + h0.w);
    float hs1 = (h1.x + h1.y) + (h1.z + h1.w);
    #pragma unroll
    for (int o = 16; o > 0; o >>= 1) {
        hs0 += __shfl_xor_sync(0xffffffffu, hs0, o);
        hs1 += __shfl_xor_sync(0xffffffffu, hs1, o);
    }

    float     s    = 0.0f;
    long long hot0 = 0, hot1 = 0;

    // Prologue: every warp has >= 1 chunk (nw*32 = 303104 < TOTAL).
    // NIDS % 32 == 0: each 32-id chunk lies entirely within one feature
    // (feat is warp-uniform).
    int base = wg * 32;
    int feat, cell;
    {
        const int idx = base + lane;
        feat = (idx >= NIDS) ? 1 : 0;
        const int i = idx - (feat ? NIDS : 0);
        int id;
        if (is64) id = (int)__ldcs((const long long*)(feat ? ids1v : ids0v) + i);
        else      id = __ldcs((const int*)(feat ? ids1v : ids0v) + i);
        cell = __ldg((feat ? g_inv1 : g_inv0) + id);
    }

    while (base < TOTAL) {
        const int cfeat = feat;
        const int ccell = cell;
        const int cbase = base;
        base += step;

        // Prefetch next chunk's id->inv chain (overlaps current gathers).
        if (base < TOTAL) {
            const int idx = base + lane;
            feat = (idx >= NIDS) ? 1 : 0;
            const int i = idx - (feat ? NIDS : 0);
            int id;
            if (is64) id = (int)__ldcs((const long long*)(feat ? ids1v : ids0v) + i);
            else      id = __ldcs((const int*)(feat ? ids1v : ids0v) + i);
            cell = __ldg((feat ? g_inv1 : g_inv0) + id);
        }

        // Process current chunk.
        const int slot = ccell ? (ccell - 1) : (ZCH - 1);
        __stcs(out + 1 + cbase + lane, (float)slot);

        const unsigned hotm = __ballot_sync(0xffffffffu, slot == ZCH - 1);
        if (cfeat) hot1 += __popc(hotm); else hot0 += __popc(hotm);

        // Cold-row gathers (~3 of 32), prefetch-depth-2 so loads overlap.
        unsigned nh = ~hotm;
        if (nh) {
            const float* e = cfeat ? e1 : e0;
            int j = __ffs(nh) - 1; nh &= nh - 1;
            int sl = __shfl_sync(0xffffffffu, slot, j);
            float4 v = __ldcs((const float4*)(e + (size_t)sl * DIM) + lane);
            while (nh) {
                j = __ffs(nh) - 1; nh &= nh - 1;
                sl = __shfl_sync(0xffffffffu, slot, j);
                const float4 v2 =
                    __ldcs((const float4*)(e + (size_t)sl * DIM) + lane);
                s += (v.x + v.y) + (v.z + v.w);
                v = v2;
            }
            s += (v.x + v.y) + (v.z + v.w);
        }
    }

    #pragma unroll
    for (int o = 16; o > 0; o >>= 1)
        s += __shfl_down_sync(0xffffffffu, s, o);

    if (lane == 0) {
        const double t = (double)s
                       + (double)hot0 * (double)hs0
                       + (double)hot1 * (double)hs1;
        atomicAdd(&blk_acc, t);
    }
    __syncthreads();

    if (threadIdx.x == 0) {
        atomicAdd(&g_acc, blk_acc);
        __threadfence();
        const unsigned done = atomicAdd(&g_done, 1u);
        if (done == gridDim.x - 1) {              // last block finalizes
            const double total = atomicAdd(&g_acc, 0.0);
            out[0] = (float)(total / ((double)TOTAL * (double)DIM));
            g_acc  = 0.0;                          // reset for next replay
            g_done = 0u;
        }
    }
}

// ---------------------------------------------------------------------------
// Launch: 2 kernels, graph-capturable, allocation-free.
// Inputs (metadata order): ids_0, ids_1, mch_ids_0, mch_ids_1, emb_0, emb_1
// Output: [loss, remapped_0 (1M), remapped_1 (1M)] as float32.
// ---------------------------------------------------------------------------
extern "C" void kernel_launch(void* const* d_in, const int* in_sizes, int n_in,
                              void* d_out, int out_size)
{
    const void*  ids0 = d_in[0];
    const void*  ids1 = d_in[1];
    const void*  m0   = d_in[2];
    const void*  m1   = d_in[3];
    const float* e0   = (const float*)d_in[4];
    const float* e1   = (const float*)d_in[5];
    float* out = (float*)d_out;

    const int threads = 256;
    scatter_kernel<<<(2 * ZCH + threads - 1) / threads, threads>>>(m0, m1);
    sparse_arch_kernel<<<148 * 8, threads>>>(ids0, ids1, m0, e0, e1, out);
}

// round 7
// speedup vs baseline: 1.3200x; 1.0477x over previous
#include <cuda_runtime.h>
#include <cstdint>

#define NIDS   1000000
#define ZCH    400000
#define DIM    128
#define TOTAL  (2 * NIDS)
#define HASHSZ 4000000

// Static scratch (no allocations allowed). Zero-initialized at module load.
// inv maps store slot+1; 0 means "unmatched" -> collision slot ZCH-1.
// Entries are rewritten identically by scatter_kernel on every launch.
__device__ double   g_acc;
__device__ unsigned g_done;
__device__ int      g_inv0[HASHSZ];
__device__ int      g_inv1[HASHSZ];

// Table values < 4M < 2^22: if the buffer is int64, the odd 32-bit words of
// the first entries are all 0; sorted random int32 data -> essentially never.
__device__ __forceinline__ bool sniff_is64(const unsigned* __restrict__ w) {
    return (w[1] | w[3] | w[5] | w[7]) == 0u;
}

// ---------------------------------------------------------------------------
// 1) Scatter slot+1 into the inverse maps. lower_bound semantics: first
//    occurrence wins for duplicates (branch on sorted neighbor, no atomics).
// ---------------------------------------------------------------------------
__global__ __launch_bounds__(256) void scatter_kernel(
    const void* __restrict__ m0v, const void* __restrict__ m1v)
{
    const int tid = blockIdx.x * blockDim.x + threadIdx.x;
    if (tid >= 2 * ZCH) return;
    const int feat = (tid >= ZCH) ? 1 : 0;
    const int j    = feat ? (tid - ZCH) : tid;
    const void* mv = feat ? m1v : m0v;
    int* inv       = feat ? g_inv1 : g_inv0;

    const bool is64 = sniff_is64((const unsigned*)m0v);
    int id, prev = -1;
    if (is64) {
        const long long* m = (const long long*)mv;
        id = (int)m[j];
        if (j > 0) prev = (int)m[j - 1];
    } else {
        const int* m = (const int*)mv;
        id = m[j];
        if (j > 0) prev = m[j - 1];
    }
    if (j == 0 || prev != id) inv[id] = j + 1;
}

// ---------------------------------------------------------------------------
// 2) Main: depth-2 modulo-scheduled pipeline. Per iteration:
//      - consume cell(n)   [inv load issued 1 full iteration ago]
//      - issue  inv(n+1)   [from id loaded 1 full iteration ago]
//      - issue  id(n+2)
//    so both random-load stages get a whole iteration of latency slack.
//    Hot-row contribution folded algebraically; last-block finalize.
// ---------------------------------------------------------------------------
__global__ __launch_bounds__(256) void sparse_arch_kernel(
    const void* __restrict__ ids0v, const void* __restrict__ ids1v,
    const void* __restrict__ m0v,
    const float* __restrict__ e0,   const float* __restrict__ e1,
    float* __restrict__ out)
{
    __shared__ double blk_acc;
    if (threadIdx.x == 0) blk_acc = 0.0;
    __syncthreads();

    const int  lane = threadIdx.x & 31;
    const int  wpb  = blockDim.x >> 5;
    const int  wg   = blockIdx.x * wpb + (threadIdx.x >> 5);
    const int  nw   = gridDim.x * wpb;
    const int  step = nw * 32;
    const bool is64 = sniff_is64((const unsigned*)m0v);

    // Streaming id load for chunk at 'b' (guarded: clamped to 0 when OOB;
    // the result is never consumed in that case). feat is warp-uniform
    // because NIDS % 32 == 0.
    auto load_id = [&](int b, int& feat_o) -> int {
        const int bb  = (b < TOTAL) ? b : 0;
        const int idx = bb + lane;
        const int f   = (idx >= NIDS) ? 1 : 0;
        const int i   = idx - (f ? NIDS : 0);
        feat_o = f;
        if (is64)  // little-endian low word; values < 2^22
            return __ldcs((const int*)(f ? ids1v : ids0v) + (i << 1));
        else
            return __ldcs((const int*)(f ? ids1v : ids0v) + i);
    };

    // Collision-row sums (broadcast to all lanes), computed once per warp.
    const float4 h0 = ((const float4*)(e0 + (size_t)(ZCH - 1) * DIM))[lane];
    const float4 h1 = ((const float4*)(e1 + (size_t)(ZCH - 1) * DIM))[lane];
    float hs0 = (h0.x + h0.y) + (h0.z + h0.w);
    float hs1 = (h1.x + h1.y) + (h1.z + h1.w);
    #pragma unroll
    for (int o = 16; o > 0; o >>= 1) {
        hs0 += __shfl_xor_sync(0xffffffffu, hs0, o);
        hs1 += __shfl_xor_sync(0xffffffffu, hs1, o);
    }

    float     s    = 0.0f;
    long long hot0 = 0, hot1 = 0;

    // Prologue (every warp has >= 1 chunk: step = 303104 < TOTAL).
    int featA, cellA;          // chunk n: inv result pending
    int featB, idB;            // chunk n+1: id loaded, inv not yet issued
    {
        int idA;
        idA   = load_id(wg * 32, featA);
        cellA = __ldg((featA ? g_inv1 : g_inv0) + idA);
        idB   = load_id(wg * 32 + step, featB);
    }

    for (int base = wg * 32; base < TOTAL; base += step) {
        // Issue inv(n+1) from the already-loaded idB.
        int cellB = 0;
        if (base + step < TOTAL)
            cellB = __ldg((featB ? g_inv1 : g_inv0) + idB);

        // Issue id(n+2).
        int featC;
        const int idC = load_id(base + 2 * step, featC);

        // ---- Process chunk n (cellA has had a full iteration in flight) ----
        const int slot = cellA ? (cellA - 1) : (ZCH - 1);
        __stcs(out + 1 + base + lane, (float)slot);

        const unsigned hotm = __ballot_sync(0xffffffffu, slot == ZCH - 1);
        if (featA) hot1 += __popc(hotm); else hot0 += __popc(hotm);

        // Cold-row gathers (~3 of 32), prefetch-depth-2 so loads overlap.
        unsigned nh = ~hotm;
        if (nh) {
            const float* e = featA ? e1 : e0;
            int j = __ffs(nh) - 1; nh &= nh - 1;
            int sl = __shfl_sync(0xffffffffu, slot, j);
            float4 v = __ldcs((const float4*)(e + (size_t)sl * DIM) + lane);
            while (nh) {
                j = __ffs(nh) - 1; nh &= nh - 1;
                sl = __shfl_sync(0xffffffffu, slot, j);
                const float4 v2 =
                    __ldcs((const float4*)(e + (size_t)sl * DIM) + lane);
                s += (v.x + v.y) + (v.z + v.w);
                v = v2;
            }
            s += (v.x + v.y) + (v.z + v.w);
        }

        // Rotate pipeline stages.
        featA = featB; cellA = cellB;
        featB = featC; idB   = idC;
    }

    #pragma unroll
    for (int o = 16; o > 0; o >>= 1)
        s += __shfl_down_sync(0xffffffffu, s, o);

    if (lane == 0) {
        const double t = (double)s
                       + (double)hot0 * (double)hs0
                       + (double)hot1 * (double)hs1;
        atomicAdd(&blk_acc, t);
    }
    __syncthreads();

    if (threadIdx.x == 0) {
        atomicAdd(&g_acc, blk_acc);
        __threadfence();
        const unsigned done = atomicAdd(&g_done, 1u);
        if (done == gridDim.x - 1) {              // last block finalizes
            const double total = atomicAdd(&g_acc, 0.0);
            out[0] = (float)(total / ((double)TOTAL * (double)DIM));
            g_acc  = 0.0;                          // reset for next replay
            g_done = 0u;
        }
    }
}

// ---------------------------------------------------------------------------
// Launch: 2 kernels, graph-capturable, allocation-free.
// Inputs (metadata order): ids_0, ids_1, mch_ids_0, mch_ids_1, emb_0, emb_1
// Output: [loss, remapped_0 (1M), remapped_1 (1M)] as float32.
// ---------------------------------------------------------------------------
extern "C" void kernel_launch(void* const* d_in, const int* in_sizes, int n_in,
                              void* d_out, int out_size)
{
    const void*  ids0 = d_in[0];
    const void*  ids1 = d_in[1];
    const void*  m0   = d_in[2];
    const void*  m1   = d_in[3];
    const float* e0   = (const float*)d_in[4];
    const float* e1   = (const float*)d_in[5];
    float* out = (float*)d_out;

    const int threads = 256;
    scatter_kernel<<<(2 * ZCH + threads - 1) / threads, threads>>>(m0, m1);
    sparse_arch_kernel<<<148 * 8, threads>>>(ids0, ids1, m0, e0, e1, out);
}